// round 8
// baseline (speedup 1.0000x reference)
#include <cuda_runtime.h>
#include <cstdint>

#define D 128
#define ROW_BYTES 512                     // 128 fp32
#define SLOTS 12                          // 2 batch rows x 6 tables
#define STAGE_BYTES (SLOTS * ROW_BYTES)   // 6144 B per stage
#define WPB 4                             // warps per block
#define STAGES 2
#define SMEM_BYTES (WPB * STAGES * STAGE_BYTES)  // 49152 = 48KB static

__device__ __forceinline__ void cp_row(unsigned int dst, const float* __restrict__ src, int lane)
{
    asm volatile("cp.async.cg.shared.global [%0], [%1], 16;\n"
                 :: "r"(dst + lane * 16), "l"(src + lane * 4) : "memory");
}

__device__ __forceinline__ void stage_task(
    unsigned int sbase, const int* __restrict__ x, int task, int bs, int lane,
    const float* __restrict__ tb, const float* __restrict__ ta,
    const float* __restrict__ tc, const float* __restrict__ cb,
    const float* __restrict__ ca, const float* __restrict__ cc)
{
    const int r0 = task * 2, r1 = r0 + 1;
    int a0, a1, a2, b0, b1, b2;
    if (r1 < bs) {
        const int2* p = (const int2*)(x + (size_t)task * 6);
        int2 q0 = __ldg(p + 0), q1 = __ldg(p + 1), q2 = __ldg(p + 2);
        a0 = q0.x; a1 = q0.y; a2 = q1.x;
        b0 = q1.y; b1 = q2.x; b2 = q2.y;
    } else {
        a0 = __ldg(x + r0 * 3 + 0);
        a1 = __ldg(x + r0 * 3 + 1);
        a2 = __ldg(x + r0 * 3 + 2);
        b0 = a0; b1 = a1; b2 = a2;
    }
    cp_row(sbase + 0  * ROW_BYTES, tb + (size_t)a0 * D, lane);
    cp_row(sbase + 1  * ROW_BYTES, ta + (size_t)a1 * D, lane);
    cp_row(sbase + 2  * ROW_BYTES, tc + (size_t)a2 * D, lane);
    cp_row(sbase + 3  * ROW_BYTES, cb + (size_t)a0 * D, lane);
    cp_row(sbase + 4  * ROW_BYTES, ca + (size_t)a1 * D, lane);
    cp_row(sbase + 5  * ROW_BYTES, cc + (size_t)a2 * D, lane);
    cp_row(sbase + 6  * ROW_BYTES, tb + (size_t)b0 * D, lane);
    cp_row(sbase + 7  * ROW_BYTES, ta + (size_t)b1 * D, lane);
    cp_row(sbase + 8  * ROW_BYTES, tc + (size_t)b2 * D, lane);
    cp_row(sbase + 9  * ROW_BYTES, cb + (size_t)b0 * D, lane);
    cp_row(sbase + 10 * ROW_BYTES, ca + (size_t)b1 * D, lane);
    cp_row(sbase + 11 * ROW_BYTES, cc + (size_t)b2 * D, lane);
}

__device__ __forceinline__ void compute_store(
    const char* __restrict__ sp, int task, int bs, int lane,
    float w0, float w1, float w2, float v0, float v1, float v2,
    float* __restrict__ out)
{
    const char* base = sp + lane * 16;
    float4 t0b = *(const float4*)(base + 0  * ROW_BYTES);
    float4 t0a = *(const float4*)(base + 1  * ROW_BYTES);
    float4 t0c = *(const float4*)(base + 2  * ROW_BYTES);
    float4 c0b = *(const float4*)(base + 3  * ROW_BYTES);
    float4 c0a = *(const float4*)(base + 4  * ROW_BYTES);
    float4 c0c = *(const float4*)(base + 5  * ROW_BYTES);
    float4 t1b = *(const float4*)(base + 6  * ROW_BYTES);
    float4 t1a = *(const float4*)(base + 7  * ROW_BYTES);
    float4 t1c = *(const float4*)(base + 8  * ROW_BYTES);
    float4 c1b = *(const float4*)(base + 9  * ROW_BYTES);
    float4 c1a = *(const float4*)(base + 10 * ROW_BYTES);
    float4 c1c = *(const float4*)(base + 11 * ROW_BYTES);

    float tx, cx, p0, p1;
    tx = w0 * t0b.x + w1 * t0a.x + w2 * t0c.x;
    cx = v0 * c0b.x + v1 * c0a.x + v2 * c0c.x;
    p0 = tx * cx;
    tx = w0 * t0b.y + w1 * t0a.y + w2 * t0c.y;
    cx = v0 * c0b.y + v1 * c0a.y + v2 * c0c.y;
    p0 += tx * cx;
    tx = w0 * t0b.z + w1 * t0a.z + w2 * t0c.z;
    cx = v0 * c0b.z + v1 * c0a.z + v2 * c0c.z;
    p0 += tx * cx;
    tx = w0 * t0b.w + w1 * t0a.w + w2 * t0c.w;
    cx = v0 * c0b.w + v1 * c0a.w + v2 * c0c.w;
    p0 += tx * cx;

    tx = w0 * t1b.x + w1 * t1a.x + w2 * t1c.x;
    cx = v0 * c1b.x + v1 * c1a.x + v2 * c1c.x;
    p1 = tx * cx;
    tx = w0 * t1b.y + w1 * t1a.y + w2 * t1c.y;
    cx = v0 * c1b.y + v1 * c1a.y + v2 * c1c.y;
    p1 += tx * cx;
    tx = w0 * t1b.z + w1 * t1a.z + w2 * t1c.z;
    cx = v0 * c1b.z + v1 * c1a.z + v2 * c1c.z;
    p1 += tx * cx;
    tx = w0 * t1b.w + w1 * t1a.w + w2 * t1c.w;
    cx = v0 * c1b.w + v1 * c1a.w + v2 * c1c.w;
    p1 += tx * cx;

    #pragma unroll
    for (int off = 16; off > 0; off >>= 1) {
        p0 += __shfl_xor_sync(0xFFFFFFFFu, p0, off);
        p1 += __shfl_xor_sync(0xFFFFFFFFu, p1, off);
    }

    if (lane == 0) {
        const int r0 = task * 2;
        float s0 = __frcp_rn(1.0f + __expf(-p0));
        float s1 = __frcp_rn(1.0f + __expf(-p1));
        if (r0 + 1 < bs) {
            *(float2*)(out + r0) = make_float2(s0, s1);
        } else {
            out[r0] = s0;
        }
    }
}

// Persistent warps; per-warp double-buffered smem stages via cp.async.
// In-flight bytes live in smem, not RF -> ~55 regs, continuous memory issue.
__global__ __launch_bounds__(128) void sgns_kernel7(
    const int*   __restrict__ x,
    const float* __restrict__ tgt_base, const float* __restrict__ tgt_a,
    const float* __restrict__ tgt_b,    const float* __restrict__ ctx_base,
    const float* __restrict__ ctx_a,    const float* __restrict__ ctx_b,
    const float* __restrict__ tgt_w,    const float* __restrict__ ctx_w,
    float* __restrict__ out, int ntasks, int bs)
{
    __shared__ __align__(16) char smem[SMEM_BYTES];

    const int lane = threadIdx.x & 31;
    const int wib  = threadIdx.x >> 5;
    const int nw   = gridDim.x * WPB;
    int t = blockIdx.x * WPB + wib;
    if (t >= ntasks) return;

    char* sA = smem + wib * (STAGES * STAGE_BYTES);
    char* sB = sA + STAGE_BYTES;
    const unsigned int a32 = (unsigned int)__cvta_generic_to_shared(sA);
    const unsigned int b32 = (unsigned int)__cvta_generic_to_shared(sB);

    // softmax weights (uniform)
    float tw0 = __ldg(&tgt_w[0]), tw1 = __ldg(&tgt_w[1]), tw2 = __ldg(&tgt_w[2]);
    float tm  = fmaxf(tw0, fmaxf(tw1, tw2));
    float te0 = __expf(tw0 - tm), te1 = __expf(tw1 - tm), te2 = __expf(tw2 - tm);
    float ti  = __frcp_rn(te0 + te1 + te2);
    const float w0 = te0 * ti, w1 = te1 * ti, w2 = te2 * ti;

    float cw0 = __ldg(&ctx_w[0]), cw1 = __ldg(&ctx_w[1]), cw2 = __ldg(&ctx_w[2]);
    float cm  = fmaxf(cw0, fmaxf(cw1, cw2));
    float ce0 = __expf(cw0 - cm), ce1 = __expf(cw1 - cm), ce2 = __expf(cw2 - cm);
    float ci  = __frcp_rn(ce0 + ce1 + ce2);
    const float v0 = ce0 * ci, v1 = ce1 * ci, v2 = ce2 * ci;

    // ---- pipeline prologue: 2 groups in flight ----
    stage_task(a32, x, t, bs, lane, tgt_base, tgt_a, tgt_b, ctx_base, ctx_a, ctx_b);
    asm volatile("cp.async.commit_group;" ::: "memory");
    if (t + nw < ntasks)
        stage_task(b32, x, t + nw, bs, lane, tgt_base, tgt_a, tgt_b, ctx_base, ctx_a, ctx_b);
    asm volatile("cp.async.commit_group;" ::: "memory");

    int cur = 0;
    while (t + nw < ntasks) {
        asm volatile("cp.async.wait_group 1;" ::: "memory");
        const char* sp  = cur ? sB : sA;
        const unsigned int s32 = cur ? b32 : a32;

        compute_store(sp, t, bs, lane, w0, w1, w2, v0, v1, v2, out);

        const int ts = t + 2 * nw;                 // refill the buffer just freed
        if (ts < ntasks)
            stage_task(s32, x, ts, bs, lane, tgt_base, tgt_a, tgt_b, ctx_base, ctx_a, ctx_b);
        asm volatile("cp.async.commit_group;" ::: "memory");

        cur ^= 1;
        t += nw;
    }

    asm volatile("cp.async.wait_group 0;" ::: "memory");
    compute_store(cur ? sB : sA, t, bs, lane, w0, w1, w2, v0, v1, v2, out);
}

extern "C" void kernel_launch(void* const* d_in, const int* in_sizes, int n_in,
                              void* d_out, int out_size)
{
    const int*   x        = (const int*)  d_in[0];
    const float* tgt_base = (const float*)d_in[1];
    const float* tgt_a    = (const float*)d_in[2];
    const float* tgt_b    = (const float*)d_in[3];
    const float* ctx_base = (const float*)d_in[4];
    const float* ctx_a    = (const float*)d_in[5];
    const float* ctx_b    = (const float*)d_in[6];
    const float* tgt_w    = (const float*)d_in[7];
    const float* ctx_w    = (const float*)d_in[8];
    float* out = (float*)d_out;

    const int bs     = in_sizes[0] / 3;
    const int ntasks = (bs + 1) / 2;          // 2 batch rows per task

    const int threads = 128;                  // 4 warps
    int blocks = 592;                         // 4 blocks/SM x 148 SMs, smem-limited, all resident
    const int max_blocks = (ntasks + WPB - 1) / WPB;
    if (blocks > max_blocks) blocks = max_blocks;

    sgns_kernel7<<<blocks, threads>>>(x, tgt_base, tgt_a, tgt_b,
                                      ctx_base, ctx_a, ctx_b,
                                      tgt_w, ctx_w, out, ntasks, bs);
}

// round 10
// speedup vs baseline: 1.2353x; 1.2353x over previous
#include <cuda_runtime.h>
#include <cstdint>

#define D 128

union V32 { unsigned long long u[4]; float f[8]; float2 f2[4]; };

// 256-bit non-coherent load with L2::evict_last (only legal width for the
// evict_last modifier on sm_103 per ptxas). 32B aligned by construction.
__device__ __forceinline__ V32 ldg256_el(const float* p)
{
    V32 v;
    asm volatile("ld.global.nc.L2::evict_last.v4.b64 {%0,%1,%2,%3}, [%4];"
                 : "=l"(v.u[0]), "=l"(v.u[1]), "=l"(v.u[2]), "=l"(v.u[3])
                 : "l"(p));
    return v;
}

__global__ __launch_bounds__(64) void sgns_kernel9b(
    const int*   __restrict__ x,        // [BS, 1, 3] int32
    const float* __restrict__ tgt_base,
    const float* __restrict__ tgt_a,
    const float* __restrict__ tgt_b,
    const float* __restrict__ ctx_base,
    const float* __restrict__ ctx_a,
    const float* __restrict__ ctx_b,
    const float* __restrict__ tgt_w,    // [3,1]
    const float* __restrict__ ctx_w,    // [3,1]
    float*       __restrict__ out,      // [BS]
    int bs)
{
    const int warp = (blockIdx.x * blockDim.x + threadIdx.x) >> 5;
    const int lane = threadIdx.x & 31;
    const int half = lane >> 4;          // 0: row r0, 1: row r1
    const int sub  = lane & 15;          // 16 lanes x 8 floats = 128
    const int r0 = warp * 2;
    if (r0 >= bs) return;
    const bool has_r1 = (r0 + 1 < bs);

    // 6 indices as 3x int2; each half-warp picks its row's triple
    const int2 xa = __ldg((const int2*)(x + (size_t)warp * 6) + 0);
    const int2 xb = __ldg((const int2*)(x + (size_t)warp * 6) + 1);
    const int2 xc = __ldg((const int2*)(x + (size_t)warp * 6) + 2);
    int i0, i1, i2;
    if (half == 0 || !has_r1) { i0 = xa.x; i1 = xa.y; i2 = xb.x; }
    else                      { i0 = xb.y; i1 = xc.x; i2 = xc.y; }

    // 6 LDG.256 per warp: each covers BOTH rows (one per half-warp)
    const int off = sub * 8;   // float offset within the 128-dim row
    V32 tb = ldg256_el(tgt_base + (size_t)i0 * D + off);
    V32 ta = ldg256_el(tgt_a    + (size_t)i1 * D + off);
    V32 tc = ldg256_el(tgt_b    + (size_t)i2 * D + off);
    V32 cb = ldg256_el(ctx_base + (size_t)i0 * D + off);
    V32 ca = ldg256_el(ctx_a    + (size_t)i1 * D + off);
    V32 cc = ldg256_el(ctx_b    + (size_t)i2 * D + off);

    // softmax weights — overlap with gather latency
    float tw0 = __ldg(&tgt_w[0]), tw1 = __ldg(&tgt_w[1]), tw2 = __ldg(&tgt_w[2]);
    float tm  = fmaxf(tw0, fmaxf(tw1, tw2));
    float te0 = __expf(tw0 - tm), te1 = __expf(tw1 - tm), te2 = __expf(tw2 - tm);
    float ti  = __frcp_rn(te0 + te1 + te2);
    const float w0 = te0 * ti, w1 = te1 * ti, w2 = te2 * ti;

    float cw0 = __ldg(&ctx_w[0]), cw1 = __ldg(&ctx_w[1]), cw2 = __ldg(&ctx_w[2]);
    float cm  = fmaxf(cw0, fmaxf(cw1, cw2));
    float ce0 = __expf(cw0 - cm), ce1 = __expf(cw1 - cm), ce2 = __expf(cw2 - cm);
    float ci  = __frcp_rn(ce0 + ce1 + ce2);
    const float v0 = ce0 * ci, v1 = ce1 * ci, v2 = ce2 * ci;

    // per-lane partial dot over 8 elements
    float p = 0.0f;
    #pragma unroll
    for (int j = 0; j < 8; j++) {
        float t = w0 * tb.f[j] + w1 * ta.f[j] + w2 * tc.f[j];
        float c = v0 * cb.f[j] + v1 * ca.f[j] + v2 * cc.f[j];
        p += t * c;
    }

    // reduce within each 16-lane half (xor 1..8 stays inside the half)
    #pragma unroll
    for (int o = 8; o > 0; o >>= 1)
        p += __shfl_xor_sync(0xFFFFFFFFu, p, o);

    // swap halves so lane 0 sees row1's sum too
    float q = __shfl_xor_sync(0xFFFFFFFFu, p, 16);

    if (lane == 0) {
        float s0 = __frcp_rn(1.0f + __expf(-p));
        float s1 = __frcp_rn(1.0f + __expf(-q));
        if (has_r1) {
            *(float2*)(out + r0) = make_float2(s0, s1);
        } else {
            out[r0] = s0;
        }
    }
}

extern "C" void kernel_launch(void* const* d_in, const int* in_sizes, int n_in,
                              void* d_out, int out_size)
{
    const int*   x        = (const int*)  d_in[0];
    const float* tgt_base = (const float*)d_in[1];
    const float* tgt_a    = (const float*)d_in[2];
    const float* tgt_b    = (const float*)d_in[3];
    const float* ctx_base = (const float*)d_in[4];
    const float* ctx_a    = (const float*)d_in[5];
    const float* ctx_b    = (const float*)d_in[6];
    const float* tgt_w    = (const float*)d_in[7];
    const float* ctx_w    = (const float*)d_in[8];
    float* out = (float*)d_out;

    const int bs = in_sizes[0] / 3;
    const int threads = 64;                  // 2 warps/block
    const int rows_per_block = (threads / 32) * 2;
    const int blocks = (bs + rows_per_block - 1) / rows_per_block;

    sgns_kernel9b<<<blocks, threads>>>(x, tgt_base, tgt_a, tgt_b,
                                       ctx_base, ctx_a, ctx_b,
                                       tgt_w, ctx_w, out, bs);
}